// round 12
// baseline (speedup 1.0000x reference)
#include <cuda_runtime.h>
#include <cstdint>

#define NN 4096
#define NWORDS (NN/32)
typedef unsigned long long ull;

// ---------------- scratch (static device globals; no allocs) ----------------
__device__ uint32_t g_adjbits[NN * NWORDS];          // 2 MB packed mask
__device__ float g_Wcat[256 * 256];                  // concat head weights [K][4*64]
__device__ float g_Wh1[NN * 256];                    // layer1 V  [N][256] (feature = h*64+f)
__device__ float g_SA1[4 * NN], g_SC1[4 * NN];
__device__ float2 g_SBD1[4 * NN];                    // (B, D) interleaved
__device__ float g_part1[8][NN * 256];               // j-split numerator slabs
__device__ float g_dpart1[8][NN * 4];                // j-split denominator slabs
__device__ float g_h1[NN * 256];                     // layer1 output (elu)
__device__ float g_Wh2[NN * 128];                    // layer2 V
__device__ float g_SA2[NN], g_SC2[NN];
__device__ float2 g_SBD2[NN];
__device__ float g_part2[16][NN * 128];
__device__ float g_dpart2[16][NN];

// ---------------- helpers ----------------
__device__ __forceinline__ void ffma2(ull& d, ull a, ull b) {
    asm("fma.rn.f32x2 %0, %1, %2, %3;" : "=l"(d) : "l"(a), "l"(b), "l"(d));
}
__device__ __forceinline__ float eluf(float x) { return x > 0.f ? x : (expf(x) - 1.f); }

// ---------------- fused: pack adjacency + Wcat transpose (one launch) ----------------
__global__ void k_packwcat(const int* __restrict__ adj, const float* __restrict__ Wh) {
    if (blockIdx.x < NN * 16 / 8) {
        int warp = threadIdx.x >> 5, lane = threadIdx.x & 31;
        int gw = blockIdx.x * 8 + warp;              // NN*16 tasks (8 words each)
        int row = gw >> 4, w0 = (gw & 15) * 8;
        const int* p = adj + (size_t)row * NN + w0 * 32;
#pragma unroll
        for (int k = 0; k < 8; k++) {
            uint32_t b = __ballot_sync(0xffffffffu, p[k * 32 + lane] > 0);
            if (lane == 0) g_adjbits[row * NWORDS + w0 + k] = b;
        }
    } else {
        int idx = (blockIdx.x - NN * 16 / 8) * 256 + threadIdx.x;   // 65536
        int h = idx >> 14, rem = idx & 16383, k = rem >> 6, f = rem & 63;
        g_Wcat[k * 256 + h * 64 + f] = Wh[idx];
    }
}

// ---------------- GEMM: C[M,Nn] = A[M,256] @ B[256,Nn] ----------------
template <int LAYER>
__global__ void __launch_bounds__(128) k_gemm(const float* __restrict__ Ain,
                                              const float* __restrict__ Bin) {
    const float* A;  const float* B;  float* C;  int Nn;
    if constexpr (LAYER == 1) { A = Ain;  B = g_Wcat; C = g_Wh1; Nn = 256; }
    else                      { A = g_h1; B = Bin;    C = g_Wh2; Nn = 128; }
    __shared__ float As[32][68];   // transposed A tile [k][m]
    __shared__ float Bs[32][64];
    int tid = threadIdx.x;
    int tx = tid & 15, ty = tid >> 4;
    int m0 = blockIdx.x * 64, n0 = blockIdx.y * 64;
    float acc[8][4] = {};
    for (int kk = 0; kk < 256; kk += 32) {
#pragma unroll
        for (int it = 0; it < 4; it++) {
            int idx = tid * 4 + it * 512;
            int i = idx >> 5, jj = idx & 31;
            float4 va = *(const float4*)(A + (size_t)(m0 + i) * 256 + kk + jj);
            As[jj + 0][i] = va.x; As[jj + 1][i] = va.y; As[jj + 2][i] = va.z; As[jj + 3][i] = va.w;
            int k2 = idx >> 6, n2 = idx & 63;
            *(float4*)&Bs[k2][n2] = *(const float4*)(B + (size_t)(kk + k2) * Nn + n0 + n2);
        }
        __syncthreads();
#pragma unroll
        for (int k = 0; k < 32; k++) {
            float a[8], b[4];
            *(float4*)(a)     = *(float4*)&As[k][ty * 8];
            *(float4*)(a + 4) = *(float4*)&As[k][ty * 8 + 4];
            *(float4*)(b)     = *(float4*)&Bs[k][tx * 4];
#pragma unroll
            for (int i = 0; i < 8; i++)
#pragma unroll
                for (int jq = 0; jq < 4; jq++) acc[i][jq] += a[i] * b[jq];
        }
        __syncthreads();
    }
#pragma unroll
    for (int i = 0; i < 8; i++)
        *(float4*)(C + (size_t)(m0 + ty * 8 + i) * Nn + n0 + tx * 4) = *(float4*)acc[i];
}

// ---------------- per-node scores: A=exp(f1),C=exp(f1/2),(B,D)=(exp(f2),exp(f2/2)) ----------------
template <int LAYER>
__global__ void k_scores(const float* __restrict__ a) {
    constexpr int NH = (LAYER == 1) ? 4 : 1;
    constexpr int FOUT = (LAYER == 1) ? 64 : 128;
    constexpr int FT = NH * FOUT;
    const float* Wh = (LAYER == 1) ? g_Wh1 : g_Wh2;
    float* SA = (LAYER == 1) ? g_SA1 : g_SA2;
    float* SC = (LAYER == 1) ? g_SC1 : g_SC2;
    float2* SBD = (LAYER == 1) ? g_SBD1 : g_SBD2;
    int warp = threadIdx.x >> 5, lane = threadIdx.x & 31;
    int gw = blockIdx.x * 8 + warp;              // gw = h*NN + i
    int h = gw / NN, i = gw % NN;
    float s1 = 0.f, s2 = 0.f;
    for (int f = lane; f < FOUT; f += 32) {
        float v = Wh[(size_t)i * FT + h * FOUT + f];
        s1 += v * a[h * 2 * FOUT + f];
        s2 += v * a[h * 2 * FOUT + FOUT + f];
    }
#pragma unroll
    for (int off = 16; off; off >>= 1) {
        s1 += __shfl_xor_sync(0xffffffffu, s1, off);
        s2 += __shfl_xor_sync(0xffffffffu, s2, off);
    }
    if (lane == 0) {
        SA[gw] = expf(s1);        SC[gw] = expf(0.5f * s1);
        SBD[gw] = make_float2(expf(s2), expf(0.5f * s2));
    }
}

// ---------------- main masked-softmax weighted sum ----------------
// w_ij = m_ij * max(A_i*B_j, C_i*D_j)   (since C_iD_j = sqrt(A_iB_j))
// num_i = sum_j w*v_j ; den_i = sum_j w  (den accumulated by builder threads)
// Big-register-tile variant: 1 CTA/SM, 16/32 rows per warp, halved V traffic/row.
template <int LAYER>
__global__ void __launch_bounds__(256, 1) k_attn() {
    constexpr int NH = (LAYER == 1) ? 4 : 1;
    constexpr int FOUT = (LAYER == 1) ? 64 : 128;
    constexpr int WROWS = (LAYER == 1) ? 16 : 32;
    constexpr int JSPLIT = (LAYER == 1) ? 8 : 16;
    constexpr int FT = NH * FOUT;
    constexpr int FPL = FT / 32;                 // floats per lane (8 or 4)
    constexpr int BROWS = 8 * WROWS;             // rows per block (128 or 256)
    constexpr int JLEN = NN / JSPLIT;            // 512 or 256
    constexpr int LPH = 32 / NH;                 // lanes per head
    constexpr int NB = NH * BROWS;               // builder slots (512 or 256)
    constexpr int SLOTS = NB / 256;              // 2 or 1
    constexpr int HSTR = BROWS + ((NH > 1) ? 4 : 0);   // per-head stride (bank-pad)
    constexpr int ROWSTR = NH * HSTR;            // float2 per j row

    const float* V  = (LAYER == 1) ? g_Wh1 : g_Wh2;
    const float* SA = (LAYER == 1) ? g_SA1 : g_SA2;
    const float* SC = (LAYER == 1) ? g_SC1 : g_SC2;
    const float2* SBD = (LAYER == 1) ? g_SBD1 : g_SBD2;

    extern __shared__ float2 dyns[];
    float2* ws2 = dyns;                          // [32][ROWSTR] duplicated weights
    float2* sBD = dyns + 32 * ROWSTR;            // [NH*32]

    int tid = threadIdx.x, warp = tid >> 5, lane = tid & 31;
    int r0 = blockIdx.x * BROWS;
    int jsplit = blockIdx.y;
    int j0 = jsplit * JLEN;
    int myhead = lane / LPH;

    // builder identity: each thread owns SLOTS weight columns (bh, br)
    int bhv[SLOTS], brv[SLOTS], soff[SLOTS];
    float Aa[SLOTS], Cc[SLOTS], den[SLOTS];
    const uint32_t* mrow[SLOTS];
#pragma unroll
    for (int s = 0; s < SLOTS; s++) {
        int sl = tid + s * 256;
        bhv[s] = sl / BROWS;  brv[s] = sl % BROWS;
        soff[s] = bhv[s] * HSTR + brv[s];
        Aa[s] = SA[bhv[s] * NN + r0 + brv[s]];
        Cc[s] = SC[bhv[s] * NN + r0 + brv[s]];
        den[s] = 0.f;
        mrow[s] = g_adjbits + (size_t)(r0 + brv[s]) * NWORDS;
    }

    ull acc[WROWS][FPL / 2];
#pragma unroll
    for (int r = 0; r < WROWS; r++)
#pragma unroll
        for (int p = 0; p < FPL / 2; p++) acc[r][p] = 0ull;

    const ull* wbase = (const ull*)ws2 + myhead * HSTR + warp * WROWS;

    for (int jc = j0; jc < j0 + JLEN; jc += 32) {
        // stage (B,D) for this 32-j chunk
        if (tid < NH * 32) sBD[tid] = SBD[(tid >> 5) * NN + jc + (tid & 31)];
        uint32_t mw[SLOTS];
#pragma unroll
        for (int s = 0; s < SLOTS; s++) mw[s] = mrow[s][jc >> 5];
        __syncthreads();
        // build duplicated weight tile; accumulate den
#pragma unroll
        for (int s = 0; s < SLOTS; s++) {
#pragma unroll 8
            for (int jj = 0; jj < 32; jj++) {
                float2 bd = sBD[bhv[s] * 32 + jj];
                float w = fmaxf(Aa[s] * bd.x, Cc[s] * bd.y);
                w = ((mw[s] >> jj) & 1u) ? w : 0.0f;
                den[s] += w;
                ws2[jj * ROWSTR + soff[s]] = make_float2(w, w);
            }
        }
        __syncthreads();

        // ---- consume: software-pipelined V loads + LDS.128 weight pairs ----
        ull vv[2][FPL / 2];
        {
            const ulonglong2* vp = (const ulonglong2*)(V + (size_t)jc * FT + lane * FPL);
#pragma unroll
            for (int p2 = 0; p2 < FPL / 4; p2++) {
                ulonglong2 t = __ldg(vp + p2);
                vv[0][2 * p2] = t.x; vv[0][2 * p2 + 1] = t.y;
            }
        }
#pragma unroll 2
        for (int j = 0; j < 32; j++) {
            int cur = j & 1, nxt = cur ^ 1;
            int jn = (j < 31) ? (j + 1) : 31;
            {
                const ulonglong2* vp = (const ulonglong2*)(V + (size_t)(jc + jn) * FT + lane * FPL);
#pragma unroll
                for (int p2 = 0; p2 < FPL / 4; p2++) {
                    ulonglong2 t = __ldg(vp + p2);
                    vv[nxt][2 * p2] = t.x; vv[nxt][2 * p2 + 1] = t.y;
                }
            }
            const ulonglong2* wp = (const ulonglong2*)(wbase + (size_t)j * ROWSTR);
#pragma unroll
            for (int pr = 0; pr < WROWS / 2; pr++) {
                ulonglong2 wpair = wp[pr];       // LDS.128: {w_r,w_r,w_r1,w_r1}
#pragma unroll
                for (int p = 0; p < FPL / 2; p++) ffma2(acc[2 * pr][p], wpair.x, vv[cur][p]);
#pragma unroll
                for (int p = 0; p < FPL / 2; p++) ffma2(acc[2 * pr + 1][p], wpair.y, vv[cur][p]);
            }
        }
        __syncthreads();
    }

    // write deterministic partial slabs
    float* po = (LAYER == 1) ? &g_part1[jsplit][0] : &g_part2[jsplit][0];
#pragma unroll
    for (int r = 0; r < WROWS; r++) {
        int row = r0 + warp * WROWS + r;
        float outv[FPL];
#pragma unroll
        for (int p = 0; p < FPL / 2; p++) {
            outv[2 * p]     = __uint_as_float((unsigned)(acc[r][p] & 0xffffffffull));
            outv[2 * p + 1] = __uint_as_float((unsigned)(acc[r][p] >> 32));
        }
#pragma unroll
        for (int q = 0; q < FPL / 4; q++)
            *(float4*)(po + (size_t)row * FT + lane * FPL + q * 4) = *(float4*)&outv[q * 4];
    }
    // builder writes its denominators
    float* dpo = (LAYER == 1) ? &g_dpart1[jsplit][0] : &g_dpart2[jsplit][0];
#pragma unroll
    for (int s = 0; s < SLOTS; s++)
        dpo[(r0 + brv[s]) * NH + bhv[s]] = den[s];
}

// ---------------- reduce slabs, normalize, ELU ----------------
__global__ void k_norm1() {
    int idx = blockIdx.x * 256 + threadIdx.x;    // N*256
    int i = idx >> 8, c = idx & 255, h = c >> 6;
    float s = 0.f, d = 0.f;
#pragma unroll
    for (int sg = 0; sg < 8; sg++) { s += g_part1[sg][idx]; d += g_dpart1[sg][i * 4 + h]; }
    g_h1[idx] = eluf(s / d);
}
__global__ void k_norm2(float* __restrict__ out) {
    int idx = blockIdx.x * 256 + threadIdx.x;    // N*128
    int i = idx >> 7;
    float s = 0.f, d = 0.f;
#pragma unroll
    for (int sg = 0; sg < 16; sg++) { s += g_part2[sg][idx]; d += g_dpart2[sg][i]; }
    out[idx] = eluf(s / d);
}

// ---------------- launch ----------------
extern "C" void kernel_launch(void* const* d_in, const int* in_sizes, int n_in,
                              void* d_out, int out_size) {
    const float* x       = (const float*)d_in[0];
    const int*   adj     = (const int*)d_in[1];
    const float* W_heads = (const float*)d_in[2];
    const float* a_heads = (const float*)d_in[3];
    const float* W_out   = (const float*)d_in[4];
    const float* a_out   = (const float*)d_in[5];
    float* out = (float*)d_out;

    // layer1: ROWSTR = 4*(128+4)=528 float2/j ; layer2: ROWSTR = 256
    constexpr int SM1 = (32 * 528 + 4 * 32) * (int)sizeof(float2);  // 136192
    constexpr int SM2 = (32 * 256 + 1 * 32) * (int)sizeof(float2);  // 65792
    cudaFuncSetAttribute(k_attn<1>, cudaFuncAttributeMaxDynamicSharedMemorySize, SM1);
    cudaFuncSetAttribute(k_attn<2>, cudaFuncAttributeMaxDynamicSharedMemorySize, SM2);

    k_packwcat<<<NN * 16 / 8 + 256, 256>>>(adj, W_heads);   // launch 1
    k_gemm<1><<<dim3(64, 4), 128>>>(x, nullptr);            // launch 2
    k_scores<1><<<4 * NN / 8, 256>>>(a_heads);              // launch 3
    k_attn<1><<<dim3(NN / 128, 8), 256, SM1>>>();           // launch 4 (profiled)
    k_norm1<<<NN * 256 / 256, 256>>>();
    k_gemm<2><<<dim3(64, 2), 128>>>(nullptr, W_out);
    k_scores<2><<<NN / 8, 256>>>(a_out);
    k_attn<2><<<dim3(NN / 256, 16), 256, SM2>>>();
    k_norm2<<<NN * 128 / 256, 256>>>(out);
}

// round 13
// speedup vs baseline: 1.0825x; 1.0825x over previous
#include <cuda_runtime.h>
#include <cstdint>

#define NN 4096
#define NWORDS (NN/32)
typedef unsigned long long ull;

// ---------------- scratch (static device globals; no allocs) ----------------
__device__ uint32_t g_adjbits[NN * NWORDS];          // 2 MB packed mask
__device__ float g_Wcat[256 * 256];                  // concat head weights [K][4*64]
__device__ float g_Wh1[NN * 256];                    // layer1 V  [N][256] (feature = h*64+f)
__device__ float g_SA1[4 * NN], g_SC1[4 * NN];
__device__ float2 g_SBD1[4 * NN];                    // (B, D) interleaved
__device__ float g_part1[4][NN * 256];               // j-split numerator slabs
__device__ float g_dpart1[4][NN * 4];                // j-split denominator slabs
__device__ float g_h1[NN * 256];                     // layer1 output (elu)
__device__ float g_Wh2[NN * 128];                    // layer2 V
__device__ float g_SA2[NN], g_SC2[NN];
__device__ float2 g_SBD2[NN];
__device__ float g_part2[8][NN * 128];
__device__ float g_dpart2[16][NN];                   // 8 jsplits x 2 builder segments

// ---------------- helpers ----------------
__device__ __forceinline__ void ffma2(ull& d, ull a, ull b) {
    asm("fma.rn.f32x2 %0, %1, %2, %3;" : "=l"(d) : "l"(a), "l"(b), "l"(d));
}
__device__ __forceinline__ float eluf(float x) { return x > 0.f ? x : (expf(x) - 1.f); }

// ---------------- fused: pack adjacency + Wcat transpose (one launch) ----------------
__global__ void k_packwcat(const int* __restrict__ adj, const float* __restrict__ Wh) {
    if (blockIdx.x < NN * 16 / 8) {
        int warp = threadIdx.x >> 5, lane = threadIdx.x & 31;
        int gw = blockIdx.x * 8 + warp;              // NN*16 tasks (8 words each)
        int row = gw >> 4, w0 = (gw & 15) * 8;
        const int* p = adj + (size_t)row * NN + w0 * 32;
#pragma unroll
        for (int k = 0; k < 8; k++) {
            uint32_t b = __ballot_sync(0xffffffffu, p[k * 32 + lane] > 0);
            if (lane == 0) g_adjbits[row * NWORDS + w0 + k] = b;
        }
    } else {
        int idx = (blockIdx.x - NN * 16 / 8) * 256 + threadIdx.x;   // 65536
        int h = idx >> 14, rem = idx & 16383, k = rem >> 6, f = rem & 63;
        g_Wcat[k * 256 + h * 64 + f] = Wh[idx];
    }
}

// ---------------- GEMM: C[M,Nn] = A[M,256] @ B[256,Nn] ----------------
template <int LAYER>
__global__ void __launch_bounds__(128) k_gemm(const float* __restrict__ Ain,
                                              const float* __restrict__ Bin) {
    const float* A;  const float* B;  float* C;  int Nn;
    if constexpr (LAYER == 1) { A = Ain;  B = g_Wcat; C = g_Wh1; Nn = 256; }
    else                      { A = g_h1; B = Bin;    C = g_Wh2; Nn = 128; }
    __shared__ float As[32][68];   // transposed A tile [k][m]
    __shared__ float Bs[32][64];
    int tid = threadIdx.x;
    int tx = tid & 15, ty = tid >> 4;
    int m0 = blockIdx.x * 64, n0 = blockIdx.y * 64;
    float acc[8][4] = {};
    for (int kk = 0; kk < 256; kk += 32) {
#pragma unroll
        for (int it = 0; it < 4; it++) {
            int idx = tid * 4 + it * 512;
            int i = idx >> 5, jj = idx & 31;
            float4 va = *(const float4*)(A + (size_t)(m0 + i) * 256 + kk + jj);
            As[jj + 0][i] = va.x; As[jj + 1][i] = va.y; As[jj + 2][i] = va.z; As[jj + 3][i] = va.w;
            int k2 = idx >> 6, n2 = idx & 63;
            *(float4*)&Bs[k2][n2] = *(const float4*)(B + (size_t)(kk + k2) * Nn + n0 + n2);
        }
        __syncthreads();
#pragma unroll
        for (int k = 0; k < 32; k++) {
            float a[8], b[4];
            *(float4*)(a)     = *(float4*)&As[k][ty * 8];
            *(float4*)(a + 4) = *(float4*)&As[k][ty * 8 + 4];
            *(float4*)(b)     = *(float4*)&Bs[k][tx * 4];
#pragma unroll
            for (int i = 0; i < 8; i++)
#pragma unroll
                for (int jq = 0; jq < 4; jq++) acc[i][jq] += a[i] * b[jq];
        }
        __syncthreads();
    }
#pragma unroll
    for (int i = 0; i < 8; i++)
        *(float4*)(C + (size_t)(m0 + ty * 8 + i) * Nn + n0 + tx * 4) = *(float4*)acc[i];
}

// ---------------- per-node scores: A=exp(f1),C=exp(f1/2),(B,D)=(exp(f2),exp(f2/2)) ----------------
template <int LAYER>
__global__ void k_scores(const float* __restrict__ a) {
    constexpr int NH = (LAYER == 1) ? 4 : 1;
    constexpr int FOUT = (LAYER == 1) ? 64 : 128;
    constexpr int FT = NH * FOUT;
    const float* Wh = (LAYER == 1) ? g_Wh1 : g_Wh2;
    float* SA = (LAYER == 1) ? g_SA1 : g_SA2;
    float* SC = (LAYER == 1) ? g_SC1 : g_SC2;
    float2* SBD = (LAYER == 1) ? g_SBD1 : g_SBD2;
    int warp = threadIdx.x >> 5, lane = threadIdx.x & 31;
    int gw = blockIdx.x * 8 + warp;              // gw = h*NN + i
    int h = gw / NN, i = gw % NN;
    float s1 = 0.f, s2 = 0.f;
    for (int f = lane; f < FOUT; f += 32) {
        float v = Wh[(size_t)i * FT + h * FOUT + f];
        s1 += v * a[h * 2 * FOUT + f];
        s2 += v * a[h * 2 * FOUT + FOUT + f];
    }
#pragma unroll
    for (int off = 16; off; off >>= 1) {
        s1 += __shfl_xor_sync(0xffffffffu, s1, off);
        s2 += __shfl_xor_sync(0xffffffffu, s2, off);
    }
    if (lane == 0) {
        SA[gw] = expf(s1);        SC[gw] = expf(0.5f * s1);
        SBD[gw] = make_float2(expf(s2), expf(0.5f * s2));
    }
}

// ---------------- main masked-softmax weighted sum ----------------
// w_ij = m_ij * max(A_i*B_j, C_i*D_j)   (since C_iD_j = sqrt(A_iB_j))
// num_i = sum_j w*v_j ; den_i = sum_j w  (den accumulated by builder threads)
// R10 shape (16 warps/SM) + bank-conflict-free padded weight tile.
template <int LAYER>
__global__ void __launch_bounds__(256, 2) k_attn() {
    constexpr int NH = (LAYER == 1) ? 4 : 1;
    constexpr int FOUT = (LAYER == 1) ? 64 : 128;
    constexpr int WROWS = (LAYER == 1) ? 8 : 16;
    constexpr int JSPLIT = (LAYER == 1) ? 4 : 8;
    constexpr int FT = NH * FOUT;
    constexpr int FPL = FT / 32;                 // floats per lane (8 or 4)
    constexpr int BROWS = 8 * WROWS;             // rows per block (64 or 128)
    constexpr int JLEN = NN / JSPLIT;
    constexpr int LPH = 32 / NH;                 // lanes per head
    constexpr int NB = NH * BROWS;               // builder slots (256 or 128)
    constexpr int REP = 256 / NB;                // 1 or 2
    constexpr int JSEG = 32 / REP;
    constexpr int HSTR = BROWS + ((NH > 1) ? 4 : 0);   // per-head stride pad: heads 8 banks apart
    constexpr int ROWSTR = NH * HSTR;            // float2 per j row (272 or 128)

    const float* V  = (LAYER == 1) ? g_Wh1 : g_Wh2;
    const float* SA = (LAYER == 1) ? g_SA1 : g_SA2;
    const float* SC = (LAYER == 1) ? g_SC1 : g_SC2;
    const float2* SBD = (LAYER == 1) ? g_SBD1 : g_SBD2;

    extern __shared__ float2 dyns[];
    float2* ws2 = dyns;                          // [32][ROWSTR] duplicated weights
    float2* sBD = dyns + 32 * ROWSTR;            // [NH*32]

    int tid = threadIdx.x, warp = tid >> 5, lane = tid & 31;
    int r0 = blockIdx.x * BROWS;
    int jsplit = blockIdx.y;
    int j0 = jsplit * JLEN;
    int myhead = lane / LPH;

    // builder identity: owns weight column (bh, br) for j-segment bseg
    int bh = (tid % NB) / BROWS;
    int br = tid % BROWS;
    int bseg = tid / NB;                         // 0..REP-1
    int jbase = bseg * JSEG;
    float Aa = SA[bh * NN + r0 + br];
    float Cc = SC[bh * NN + r0 + br];
    float den = 0.f;
    const uint32_t* mrow = g_adjbits + (size_t)(r0 + br) * NWORDS;

    ull acc[WROWS][FPL / 2];
#pragma unroll
    for (int r = 0; r < WROWS; r++)
#pragma unroll
        for (int p = 0; p < FPL / 2; p++) acc[r][p] = 0ull;

    // consumer base pointer into the padded duplicated-weight tile
    const ull* wbase = (const ull*)ws2 + myhead * HSTR + warp * WROWS;

    for (int jc = j0; jc < j0 + JLEN; jc += 32) {
        // stage (B,D) for this 32-j chunk
        if (tid < NH * 32) sBD[tid] = SBD[(tid >> 5) * NN + jc + (tid & 31)];
        uint32_t mw = mrow[jc >> 5] >> jbase;
        __syncthreads();
        // build duplicated weight tile ws2[j][bh*HSTR+br] = {w,w}; accumulate den
#pragma unroll
        for (int jj = 0; jj < JSEG; jj++) {
            int j = jbase + jj;
            float2 bd = sBD[bh * 32 + j];
            float w = fmaxf(Aa * bd.x, Cc * bd.y);
            w = (mw & (1u << jj)) ? w : 0.0f;
            den += w;
            ws2[j * ROWSTR + bh * HSTR + br] = make_float2(w, w);
        }
        __syncthreads();

        // ---- consume: software-pipelined V loads + conflict-free LDS.128 weight pairs ----
        ull vv[2][FPL / 2];
        {
            const ulonglong2* vp = (const ulonglong2*)(V + (size_t)jc * FT + lane * FPL);
#pragma unroll
            for (int p2 = 0; p2 < FPL / 4; p2++) {
                ulonglong2 t = __ldg(vp + p2);
                vv[0][2 * p2] = t.x; vv[0][2 * p2 + 1] = t.y;
            }
        }
#pragma unroll 4
        for (int j = 0; j < 32; j++) {
            int cur = j & 1, nxt = cur ^ 1;
            int jn = (j < 31) ? (j + 1) : 31;
            {
                const ulonglong2* vp = (const ulonglong2*)(V + (size_t)(jc + jn) * FT + lane * FPL);
#pragma unroll
                for (int p2 = 0; p2 < FPL / 4; p2++) {
                    ulonglong2 t = __ldg(vp + p2);
                    vv[nxt][2 * p2] = t.x; vv[nxt][2 * p2 + 1] = t.y;
                }
            }
            const ulonglong2* wp = (const ulonglong2*)(wbase + (size_t)j * ROWSTR);
#pragma unroll
            for (int pr = 0; pr < WROWS / 2; pr++) {
                ulonglong2 wpair = wp[pr];       // LDS.128 broadcast, conflict-free
#pragma unroll
                for (int p = 0; p < FPL / 2; p++) ffma2(acc[2 * pr][p], wpair.x, vv[cur][p]);
#pragma unroll
                for (int p = 0; p < FPL / 2; p++) ffma2(acc[2 * pr + 1][p], wpair.y, vv[cur][p]);
            }
        }
        __syncthreads();
    }

    // write deterministic partial slabs
    float* po = (LAYER == 1) ? &g_part1[jsplit][0] : &g_part2[jsplit][0];
#pragma unroll
    for (int r = 0; r < WROWS; r++) {
        int row = r0 + warp * WROWS + r;
        float outv[FPL];
#pragma unroll
        for (int p = 0; p < FPL / 2; p++) {
            outv[2 * p]     = __uint_as_float((unsigned)(acc[r][p] & 0xffffffffull));
            outv[2 * p + 1] = __uint_as_float((unsigned)(acc[r][p] >> 32));
        }
#pragma unroll
        for (int q = 0; q < FPL / 4; q++)
            *(float4*)(po + (size_t)row * FT + lane * FPL + q * 4) = *(float4*)&outv[q * 4];
    }
    // builder writes its denominator
    if (LAYER == 1) g_dpart1[jsplit][(r0 + br) * 4 + bh] = den;
    else            g_dpart2[jsplit * 2 + bseg][r0 + br] = den;
}

// ---------------- reduce slabs, normalize, ELU ----------------
__global__ void k_norm1() {
    int idx = blockIdx.x * 256 + threadIdx.x;    // N*256
    int i = idx >> 8, c = idx & 255, h = c >> 6;
    float s = 0.f, d = 0.f;
#pragma unroll
    for (int sg = 0; sg < 4; sg++) { s += g_part1[sg][idx]; d += g_dpart1[sg][i * 4 + h]; }
    g_h1[idx] = eluf(s / d);
}
__global__ void k_norm2(float* __restrict__ out) {
    int idx = blockIdx.x * 256 + threadIdx.x;    // N*128
    int i = idx >> 7;
    float s = 0.f, d = 0.f;
#pragma unroll
    for (int sg = 0; sg < 8; sg++) s += g_part2[sg][idx];
#pragma unroll
    for (int sg = 0; sg < 16; sg++) d += g_dpart2[sg][i];
    out[idx] = eluf(s / d);
}

// ---------------- launch ----------------
extern "C" void kernel_launch(void* const* d_in, const int* in_sizes, int n_in,
                              void* d_out, int out_size) {
    const float* x       = (const float*)d_in[0];
    const int*   adj     = (const int*)d_in[1];
    const float* W_heads = (const float*)d_in[2];
    const float* a_heads = (const float*)d_in[3];
    const float* W_out   = (const float*)d_in[4];
    const float* a_out   = (const float*)d_in[5];
    float* out = (float*)d_out;

    // layer1: ROWSTR = 4*(64+4) = 272 float2/j ; layer2: ROWSTR = 128
    constexpr int SM1 = (32 * 272 + 4 * 32) * (int)sizeof(float2);  // 70656
    constexpr int SM2 = (32 * 128 + 1 * 32) * (int)sizeof(float2);  // 33024
    cudaFuncSetAttribute(k_attn<1>, cudaFuncAttributeMaxDynamicSharedMemorySize, SM1);
    cudaFuncSetAttribute(k_attn<2>, cudaFuncAttributeMaxDynamicSharedMemorySize, SM2);

    k_packwcat<<<NN * 16 / 8 + 256, 256>>>(adj, W_heads);   // launch 1
    k_gemm<1><<<dim3(64, 4), 128>>>(x, nullptr);            // launch 2
    k_scores<1><<<4 * NN / 8, 256>>>(a_heads);              // launch 3
    k_attn<1><<<dim3(NN / 64, 4), 256, SM1>>>();            // launch 4 (profiled)
    k_norm1<<<NN * 256 / 256, 256>>>();
    k_gemm<2><<<dim3(64, 2), 128>>>(nullptr, W_out);
    k_scores<2><<<NN / 8, 256>>>(a_out);
    k_attn<2><<<dim3(NN / 128, 8), 256, SM2>>>();
    k_norm2<<<NN * 128 / 256, 256>>>(out);
}

// round 14
// speedup vs baseline: 1.0896x; 1.0065x over previous
#include <cuda_runtime.h>
#include <cstdint>

#define NN 4096
#define NWORDS (NN/32)
typedef unsigned long long ull;

// ---------------- scratch (static device globals; no allocs) ----------------
__device__ uint32_t g_adjbits[NN * NWORDS];          // 2 MB packed mask
__device__ float g_Wcat[256 * 256];                  // concat head weights [K][4*64]
__device__ float g_Wh1[NN * 256];                    // layer1 V  [N][256] (feature = h*64+f)
__device__ float g_SA1[4 * NN], g_SC1[4 * NN];
__device__ float2 g_SBD1[4 * NN];                    // (B, D) interleaved
__device__ float g_part1[4][NN * 256];               // j-split numerator slabs
__device__ float g_dpart1[4][NN * 4];                // j-split denominator slabs
__device__ float g_h1[NN * 256];                     // layer1 output (elu)
__device__ float g_Wh2[NN * 128];                    // layer2 V
__device__ float g_SA2[NN], g_SC2[NN];
__device__ float2 g_SBD2[NN];
__device__ float g_part2[8][NN * 128];
__device__ float g_dpart2[16][NN];                   // 8 jsplits x 2 builder segments

// ---------------- helpers ----------------
__device__ __forceinline__ void ffma2(ull& d, ull a, ull b) {
    asm("fma.rn.f32x2 %0, %1, %2, %3;" : "=l"(d) : "l"(a), "l"(b), "l"(d));
}
__device__ __forceinline__ float eluf(float x) { return x > 0.f ? x : (expf(x) - 1.f); }

// ---------------- fused: pack adjacency + Wcat transpose (one launch) ----------------
__global__ void k_packwcat(const int* __restrict__ adj, const float* __restrict__ Wh) {
    if (blockIdx.x < NN * 16 / 8) {
        int warp = threadIdx.x >> 5, lane = threadIdx.x & 31;
        int gw = blockIdx.x * 8 + warp;              // NN*16 tasks (8 words each)
        int row = gw >> 4, w0 = (gw & 15) * 8;
        const int* p = adj + (size_t)row * NN + w0 * 32;
#pragma unroll
        for (int k = 0; k < 8; k++) {
            uint32_t b = __ballot_sync(0xffffffffu, p[k * 32 + lane] > 0);
            if (lane == 0) g_adjbits[row * NWORDS + w0 + k] = b;
        }
    } else {
        int idx = (blockIdx.x - NN * 16 / 8) * 256 + threadIdx.x;   // 65536
        int h = idx >> 14, rem = idx & 16383, k = rem >> 6, f = rem & 63;
        g_Wcat[k * 256 + h * 64 + f] = Wh[idx];
    }
}

// ---------------- GEMM: C[M,Nn] = A[M,256] @ B[256,Nn] ----------------
template <int LAYER>
__global__ void __launch_bounds__(128) k_gemm(const float* __restrict__ Ain,
                                              const float* __restrict__ Bin) {
    const float* A;  const float* B;  float* C;  int Nn;
    if constexpr (LAYER == 1) { A = Ain;  B = g_Wcat; C = g_Wh1; Nn = 256; }
    else                      { A = g_h1; B = Bin;    C = g_Wh2; Nn = 128; }
    __shared__ float As[32][68];   // transposed A tile [k][m]
    __shared__ float Bs[32][64];
    int tid = threadIdx.x;
    int tx = tid & 15, ty = tid >> 4;
    int m0 = blockIdx.x * 64, n0 = blockIdx.y * 64;
    float acc[8][4] = {};
    for (int kk = 0; kk < 256; kk += 32) {
#pragma unroll
        for (int it = 0; it < 4; it++) {
            int idx = tid * 4 + it * 512;
            int i = idx >> 5, jj = idx & 31;
            float4 va = *(const float4*)(A + (size_t)(m0 + i) * 256 + kk + jj);
            As[jj + 0][i] = va.x; As[jj + 1][i] = va.y; As[jj + 2][i] = va.z; As[jj + 3][i] = va.w;
            int k2 = idx >> 6, n2 = idx & 63;
            *(float4*)&Bs[k2][n2] = *(const float4*)(B + (size_t)(kk + k2) * Nn + n0 + n2);
        }
        __syncthreads();
#pragma unroll
        for (int k = 0; k < 32; k++) {
            float a[8], b[4];
            *(float4*)(a)     = *(float4*)&As[k][ty * 8];
            *(float4*)(a + 4) = *(float4*)&As[k][ty * 8 + 4];
            *(float4*)(b)     = *(float4*)&Bs[k][tx * 4];
#pragma unroll
            for (int i = 0; i < 8; i++)
#pragma unroll
                for (int jq = 0; jq < 4; jq++) acc[i][jq] += a[i] * b[jq];
        }
        __syncthreads();
    }
#pragma unroll
    for (int i = 0; i < 8; i++)
        *(float4*)(C + (size_t)(m0 + ty * 8 + i) * Nn + n0 + tx * 4) = *(float4*)acc[i];
}

// ---------------- per-node scores: A=exp(f1),C=exp(f1/2),(B,D)=(exp(f2),exp(f2/2)) ----------------
template <int LAYER>
__global__ void k_scores(const float* __restrict__ a) {
    constexpr int NH = (LAYER == 1) ? 4 : 1;
    constexpr int FOUT = (LAYER == 1) ? 64 : 128;
    constexpr int FT = NH * FOUT;
    const float* Wh = (LAYER == 1) ? g_Wh1 : g_Wh2;
    float* SA = (LAYER == 1) ? g_SA1 : g_SA2;
    float* SC = (LAYER == 1) ? g_SC1 : g_SC2;
    float2* SBD = (LAYER == 1) ? g_SBD1 : g_SBD2;
    int warp = threadIdx.x >> 5, lane = threadIdx.x & 31;
    int gw = blockIdx.x * 8 + warp;              // gw = h*NN + i
    int h = gw / NN, i = gw % NN;
    float s1 = 0.f, s2 = 0.f;
    for (int f = lane; f < FOUT; f += 32) {
        float v = Wh[(size_t)i * FT + h * FOUT + f];
        s1 += v * a[h * 2 * FOUT + f];
        s2 += v * a[h * 2 * FOUT + FOUT + f];
    }
#pragma unroll
    for (int off = 16; off; off >>= 1) {
        s1 += __shfl_xor_sync(0xffffffffu, s1, off);
        s2 += __shfl_xor_sync(0xffffffffu, s2, off);
    }
    if (lane == 0) {
        SA[gw] = expf(s1);        SC[gw] = expf(0.5f * s1);
        SBD[gw] = make_float2(expf(s2), expf(0.5f * s2));
    }
}

// ---------------- main masked-softmax weighted sum ----------------
// w_ij = m_ij * max(A_i*B_j, C_i*D_j)   (since C_iD_j = sqrt(A_iB_j))
// num_i = sum_j w*v_j ; den_i = sum_j w  (den accumulated by builder threads)
// All consumer memory ops are LDS: V chunk staged in smem, weights padded tile.
template <int LAYER>
__global__ void __launch_bounds__(256, 2) k_attn() {
    constexpr int NH = (LAYER == 1) ? 4 : 1;
    constexpr int FOUT = (LAYER == 1) ? 64 : 128;
    constexpr int WROWS = (LAYER == 1) ? 8 : 16;
    constexpr int JSPLIT = (LAYER == 1) ? 4 : 8;
    constexpr int FT = NH * FOUT;
    constexpr int FPL = FT / 32;                 // floats per lane (8 or 4)
    constexpr int BROWS = 8 * WROWS;             // rows per block (64 or 128)
    constexpr int JLEN = NN / JSPLIT;
    constexpr int LPH = 32 / NH;                 // lanes per head
    constexpr int NB = NH * BROWS;               // builder slots (256 or 128)
    constexpr int REP = 256 / NB;                // 1 or 2
    constexpr int JSEG = 32 / REP;
    constexpr int HSTR = BROWS + ((NH > 1) ? 4 : 0);   // per-head stride pad
    constexpr int ROWSTR = NH * HSTR;            // float2 per j row (272 or 128)
    constexpr int NV4 = 32 * FT / 4;             // float4 count of V chunk (2048 or 1024)

    const float* V  = (LAYER == 1) ? g_Wh1 : g_Wh2;
    const float* SA = (LAYER == 1) ? g_SA1 : g_SA2;
    const float* SC = (LAYER == 1) ? g_SC1 : g_SC2;
    const float2* SBD = (LAYER == 1) ? g_SBD1 : g_SBD2;

    extern __shared__ float2 dyns[];
    float2* ws2 = dyns;                          // [32][ROWSTR] duplicated weights
    float2* sBD = dyns + 32 * ROWSTR;            // [NH*32]
    float*  sV  = (float*)(sBD + NH * 32);       // [32][FT] staged V chunk

    int tid = threadIdx.x, warp = tid >> 5, lane = tid & 31;
    int r0 = blockIdx.x * BROWS;
    int jsplit = blockIdx.y;
    int j0 = jsplit * JLEN;
    int myhead = lane / LPH;

    // builder identity: owns weight column (bh, br) for j-segment bseg
    int bh = (tid % NB) / BROWS;
    int br = tid % BROWS;
    int bseg = tid / NB;                         // 0..REP-1
    int jbase = bseg * JSEG;
    float Aa = SA[bh * NN + r0 + br];
    float Cc = SC[bh * NN + r0 + br];
    float den = 0.f;
    const uint32_t* mrow = g_adjbits + (size_t)(r0 + br) * NWORDS;

    ull acc[WROWS][FPL / 2];
#pragma unroll
    for (int r = 0; r < WROWS; r++)
#pragma unroll
        for (int p = 0; p < FPL / 2; p++) acc[r][p] = 0ull;

    const ull* wbase = (const ull*)ws2 + myhead * HSTR + warp * WROWS;

    for (int jc = j0; jc < j0 + JLEN; jc += 32) {
        // ---- stage phase: (B,D) pairs + V chunk into smem ----
        if (tid < NH * 32) sBD[tid] = SBD[(tid >> 5) * NN + jc + (tid & 31)];
        {
            const float4* gv = (const float4*)(V + (size_t)jc * FT);
            float4* sv4 = (float4*)sV;
#pragma unroll
            for (int q = 0; q < NV4 / 256; q++)
                sv4[tid + q * 256] = __ldg(gv + tid + q * 256);
        }
        uint32_t mw = mrow[jc >> 5] >> jbase;
        __syncthreads();
        // ---- build duplicated weight tile; accumulate den ----
#pragma unroll
        for (int jj = 0; jj < JSEG; jj++) {
            int j = jbase + jj;
            float2 bd = sBD[bh * 32 + j];
            float w = fmaxf(Aa * bd.x, Cc * bd.y);
            w = (mw & (1u << jj)) ? w : 0.0f;
            den += w;
            ws2[j * ROWSTR + bh * HSTR + br] = make_float2(w, w);
        }
        __syncthreads();
        // ---- consume: pure-LDS inner loop (29-cyc latencies, ILP loads) ----
#pragma unroll 4
        for (int j = 0; j < 32; j++) {
            ull vv[FPL / 2];
            const ulonglong2* vp = (const ulonglong2*)(sV + j * FT + lane * FPL);
#pragma unroll
            for (int p2 = 0; p2 < FPL / 4; p2++) {
                ulonglong2 t = vp[p2];
                vv[2 * p2] = t.x; vv[2 * p2 + 1] = t.y;
            }
            const ulonglong2* wp = (const ulonglong2*)(wbase + (size_t)j * ROWSTR);
            ulonglong2 wpair[WROWS / 2];
#pragma unroll
            for (int pr = 0; pr < WROWS / 2; pr++) wpair[pr] = wp[pr];
#pragma unroll
            for (int pr = 0; pr < WROWS / 2; pr++) {
#pragma unroll
                for (int p = 0; p < FPL / 2; p++) ffma2(acc[2 * pr][p], wpair[pr].x, vv[p]);
#pragma unroll
                for (int p = 0; p < FPL / 2; p++) ffma2(acc[2 * pr + 1][p], wpair[pr].y, vv[p]);
            }
        }
        __syncthreads();
    }

    // write deterministic partial slabs
    float* po = (LAYER == 1) ? &g_part1[jsplit][0] : &g_part2[jsplit][0];
#pragma unroll
    for (int r = 0; r < WROWS; r++) {
        int row = r0 + warp * WROWS + r;
        float outv[FPL];
#pragma unroll
        for (int p = 0; p < FPL / 2; p++) {
            outv[2 * p]     = __uint_as_float((unsigned)(acc[r][p] & 0xffffffffull));
            outv[2 * p + 1] = __uint_as_float((unsigned)(acc[r][p] >> 32));
        }
#pragma unroll
        for (int q = 0; q < FPL / 4; q++)
            *(float4*)(po + (size_t)row * FT + lane * FPL + q * 4) = *(float4*)&outv[q * 4];
    }
    // builder writes its denominator
    if (LAYER == 1) g_dpart1[jsplit][(r0 + br) * 4 + bh] = den;
    else            g_dpart2[jsplit * 2 + bseg][r0 + br] = den;
}

// ---------------- reduce slabs, normalize, ELU ----------------
__global__ void k_norm1() {
    int idx = blockIdx.x * 256 + threadIdx.x;    // N*256
    int i = idx >> 8, c = idx & 255, h = c >> 6;
    float s = 0.f, d = 0.f;
#pragma unroll
    for (int sg = 0; sg < 4; sg++) { s += g_part1[sg][idx]; d += g_dpart1[sg][i * 4 + h]; }
    g_h1[idx] = eluf(s / d);
}
__global__ void k_norm2(float* __restrict__ out) {
    int idx = blockIdx.x * 256 + threadIdx.x;    // N*128
    int i = idx >> 7;
    float s = 0.f, d = 0.f;
#pragma unroll
    for (int sg = 0; sg < 8; sg++) s += g_part2[sg][idx];
#pragma unroll
    for (int sg = 0; sg < 16; sg++) d += g_dpart2[sg][i];
    out[idx] = eluf(s / d);
}

// ---------------- launch ----------------
extern "C" void kernel_launch(void* const* d_in, const int* in_sizes, int n_in,
                              void* d_out, int out_size) {
    const float* x       = (const float*)d_in[0];
    const int*   adj     = (const int*)d_in[1];
    const float* W_heads = (const float*)d_in[2];
    const float* a_heads = (const float*)d_in[3];
    const float* W_out   = (const float*)d_in[4];
    const float* a_out   = (const float*)d_in[5];
    float* out = (float*)d_out;

    // layer1: ws2 32*272*8 + sBD 4*32*8 + sV 32*256*4 = 69632+1024+32768 = 103424
    // layer2: ws2 32*128*8 + sBD 32*8   + sV 32*128*4 = 32768+256+16384  = 49408
    constexpr int SM1 = 103424;
    constexpr int SM2 = 49408;
    cudaFuncSetAttribute(k_attn<1>, cudaFuncAttributeMaxDynamicSharedMemorySize, SM1);
    cudaFuncSetAttribute(k_attn<2>, cudaFuncAttributeMaxDynamicSharedMemorySize, SM2);

    k_packwcat<<<NN * 16 / 8 + 256, 256>>>(adj, W_heads);   // launch 1
    k_gemm<1><<<dim3(64, 4), 128>>>(x, nullptr);            // launch 2
    k_scores<1><<<4 * NN / 8, 256>>>(a_heads);              // launch 3
    k_attn<1><<<dim3(NN / 64, 4), 256, SM1>>>();            // launch 4 (profiled)
    k_norm1<<<NN * 256 / 256, 256>>>();
    k_gemm<2><<<dim3(64, 2), 128>>>(nullptr, W_out);
    k_scores<2><<<NN / 8, 256>>>(a_out);
    k_attn<2><<<dim3(NN / 128, 8), 256, SM2>>>();
    k_norm2<<<NN * 128 / 256, 256>>>(out);
}